// round 9
// baseline (speedup 1.0000x reference)
#include <cuda_runtime.h>
#include <cstdint>

#define NN 50000
#define EE 600000
#define PP 100000
#define FD 128

// ---- device scratch ----
__device__ float g_h1[NN * FD];
__device__ float g_h2[NN * FD];
__device__ int   g_cnt[NN];
__device__ int   g_cur[NN];
__device__ int   g_rowstart[NN + 1];
__device__ int   g_csr[EE];

typedef unsigned long long u64;

__device__ __forceinline__ void ffma2(u64& d, u64 a, u64 b) {
    asm("fma.rn.f32x2 %0, %1, %2, %0;" : "+l"(d) : "l"(a), "l"(b));
}
__device__ __forceinline__ void unpack2(float& lo, float& hi, u64 v) {
    asm("mov.b64 {%0, %1}, %2;" : "=f"(lo), "=f"(hi) : "l"(v));
}
__device__ __forceinline__ u64 pack_dup(float a) {
    u64 r;
    asm("mov.b64 %0, {%1, %1};" : "=l"(r) : "f"(a));
    return r;
}

// ============================================================================
// CSR build: count -> scan -> fill
// ============================================================================
__global__ void count_kernel(const int* __restrict__ dst)
{
    int e = blockIdx.x * blockDim.x + threadIdx.x;
    if (e < EE) atomicAdd(&g_cnt[dst[e]], 1);
}

__global__ void __launch_bounds__(1024, 1) scan_kernel()
{
    __shared__ int wsum[32];
    __shared__ int carry;
    int tid = threadIdx.x, lane = tid & 31, w = tid >> 5;
    if (tid == 0) carry = 0;
    __syncthreads();
    for (int base = 0; base < NN; base += 1024) {
        int i = base + tid;
        int v = (i < NN) ? g_cnt[i] : 0;
        int s = v;
#pragma unroll
        for (int off = 1; off < 32; off <<= 1) {
            int t = __shfl_up_sync(0xffffffffu, s, off);
            if (lane >= off) s += t;
        }
        if (lane == 31) wsum[w] = s;
        __syncthreads();
        if (w == 0) {
            int ws = wsum[lane];
#pragma unroll
            for (int off = 1; off < 32; off <<= 1) {
                int t = __shfl_up_sync(0xffffffffu, ws, off);
                if (lane >= off) ws += t;
            }
            wsum[lane] = ws;
        }
        __syncthreads();
        int prev = (w > 0) ? wsum[w - 1] : 0;
        int incl = carry + prev + s;
        if (i < NN) g_rowstart[i + 1] = incl;
        int chunk_total = wsum[31];
        __syncthreads();
        if (tid == 0) carry += chunk_total;
        __syncthreads();
    }
    if (threadIdx.x == 0) g_rowstart[0] = 0;
}

__global__ void fill_kernel(const int* __restrict__ src,
                            const int* __restrict__ dst)
{
    int e = blockIdx.x * blockDim.x + threadIdx.x;
    if (e >= EE) return;
    int d = dst[e];
    int p = atomicAdd(&g_cur[d], 1);
    g_csr[g_rowstart[d] + p] = src[e];
}

// ============================================================================
// SAGE linear with FUSED neighbor aggregation.
// out = act(src @ Ws + mean_{neighbors}(src) @ Wn + b)
// R5/R8 micro-kernel; K-half 1 activations gathered inline via CSR.
// ============================================================================
template <bool RELU>
__global__ void __launch_bounds__(512, 1)
sage_linear_kernel(const float* __restrict__ src,
                   const float* __restrict__ Ws,
                   const float* __restrict__ Wn,
                   const float* __restrict__ b,
                   float* __restrict__ out,
                   int rpb)
{
    extern __shared__ float sm[];
    float* smW   = sm;                 // [256][128]
    float* stage = sm + 256 * 128;     // [16][8][128]

    int tid  = threadIdx.x;
    int lane = tid & 31;
    int warp = tid >> 5;

    for (int i = tid; i < (128 * 128) / 4; i += blockDim.x) {
        ((float4*)smW)[i]               = ((const float4*)Ws)[i];
        ((float4*)(smW + 128 * 128))[i] = ((const float4*)Wn)[i];
    }
    __syncthreads();

    int bstart = blockIdx.x * rpb;
    int bend   = min(bstart + rpb, NN);

    float4 bias = *(const float4*)(b + lane * 4);
    float* myStage = stage + warp * (8 * 128);
    const float* hp = src + lane * 4;

    for (int base = bstart + warp * 8; base < bend; base += 128) {

        u64 acc[8][2];
#pragma unroll
        for (int r = 0; r < 8; r++) { acc[r][0] = 0ull; acc[r][1] = 0ull; }

#pragma unroll 1
        for (int h = 0; h < 2; h++) {
            // ---- stage 8 rows of this K-half (warp-local) ----
            if (h == 0) {
#pragma unroll
                for (int r = 0; r < 8; r++) {
                    int row = base + r;
                    float4 v = make_float4(0.f, 0.f, 0.f, 0.f);
                    if (row < bend)
                        v = *(const float4*)(src + row * FD + lane * 4);
                    *(float4*)(myStage + r * 128 + lane * 4) = v;
                }
            } else {
                // fused aggregate: mean over CSR neighbors of each row
#pragma unroll 1
                for (int r = 0; r < 8; r++) {
                    int row = base + r;
                    float4 m = make_float4(0.f, 0.f, 0.f, 0.f);
                    if (row < bend) {
                        int beg = g_rowstart[row], end = g_rowstart[row + 1];
                        int e = beg;
                        for (; e + 1 < end; e += 2) {
                            int s0 = g_csr[e], s1 = g_csr[e + 1];
                            float4 v0 = *(const float4*)(hp + s0 * FD);
                            float4 v1 = *(const float4*)(hp + s1 * FD);
                            m.x += v0.x + v1.x; m.y += v0.y + v1.y;
                            m.z += v0.z + v1.z; m.w += v0.w + v1.w;
                        }
                        if (e < end) {
                            int s0 = g_csr[e];
                            float4 v0 = *(const float4*)(hp + s0 * FD);
                            m.x += v0.x; m.y += v0.y; m.z += v0.z; m.w += v0.w;
                        }
                        float rd = 1.0f / fmaxf((float)(end - beg), 1.0f);
                        m.x *= rd; m.y *= rd; m.z *= rd; m.w *= rd;
                    }
                    *(float4*)(myStage + r * 128 + lane * 4) = m;
                }
            }
            __syncwarp();

            const float* wbase = smW + h * 128 * 128;
#pragma unroll 1
            for (int k = 0; k < 128; k += 4) {
                float4 xq[8];
#pragma unroll
                for (int r = 0; r < 8; r++)
                    xq[r] = *(const float4*)(myStage + r * 128 + k);
#pragma unroll
                for (int kk = 0; kk < 4; kk++) {
                    ulonglong2 w = *(const ulonglong2*)(wbase + (k + kk) * 128 + lane * 4);
#pragma unroll
                    for (int r = 0; r < 8; r++) {
                        float xs = (kk == 0) ? xq[r].x : (kk == 1) ? xq[r].y
                                 : (kk == 2) ? xq[r].z : xq[r].w;
                        u64 xx = pack_dup(xs);
                        ffma2(acc[r][0], xx, w.x);
                        ffma2(acc[r][1], xx, w.y);
                    }
                }
            }
            __syncwarp();
        }

#pragma unroll
        for (int r = 0; r < 8; r++) {
            int row = base + r;
            if (row < bend) {
                float4 o;
                unpack2(o.x, o.y, acc[r][0]);
                unpack2(o.z, o.w, acc[r][1]);
                o.x += bias.x; o.y += bias.y; o.z += bias.z; o.w += bias.w;
                if (RELU) {
                    o.x = fmaxf(o.x, 0.f); o.y = fmaxf(o.y, 0.f);
                    o.z = fmaxf(o.z, 0.f); o.w = fmaxf(o.w, 0.f);
                }
                *(float4*)(out + row * FD + lane * 4) = o;
            }
        }
    }
}

// ============================================================================
// Fused decoder (R8 form, proven)
// ============================================================================
__global__ void __launch_bounds__(512, 1)
decoder_kernel(const float* __restrict__ h,
               const int* __restrict__ ps, const int* __restrict__ pd,
               const int* __restrict__ ns, const int* __restrict__ nd,
               const float* __restrict__ Wd1, const float* __restrict__ bd1,
               const float* __restrict__ Wd2, const float* __restrict__ bd2,
               const float* __restrict__ Wd3, const float* __restrict__ bd3,
               float* __restrict__ out,
               int rpb)
{
    extern __shared__ float sm[];
    float* smW1  = sm;                 // [128][128]
    float* smW2  = sm + 128 * 128;     // [128][128]
    float* stage = sm + 2 * 128 * 128; // [16][8][128]

    int tid  = threadIdx.x;
    int lane = tid & 31;
    int warp = tid >> 5;

    for (int i = tid; i < (128 * 128) / 4; i += blockDim.x) {
        ((float4*)smW1)[i] = ((const float4*)Wd1)[i];
        ((float4*)smW2)[i] = ((const float4*)Wd2)[i];
    }
    __syncthreads();

    float4 b1v = *(const float4*)(bd1 + lane * 4);
    float4 b2v = *(const float4*)(bd2 + lane * 4);
    float4 w3v = *(const float4*)(Wd3 + lane * 4);
    float  b3  = bd3[0];

    float* myStage = stage + warp * (8 * 128);
    const int total = 2 * PP;

    int bstart = blockIdx.x * rpb;
    int bend   = min(bstart + rpb, total);

    for (int base = bstart + warp * 8; base < bend; base += 128) {
        // ---- stage z = h[s] * h[d] ----
#pragma unroll
        for (int r = 0; r < 8; r++) {
            int p = base + r;
            float4 z = make_float4(0.f, 0.f, 0.f, 0.f);
            if (p < bend) {
                int s, d;
                if (p < PP) { s = ps[p]; d = pd[p]; }
                else        { s = ns[p - PP]; d = nd[p - PP]; }
                float4 a = *(const float4*)(h + s * FD + lane * 4);
                float4 c = *(const float4*)(h + d * FD + lane * 4);
                z.x = a.x * c.x; z.y = a.y * c.y;
                z.z = a.z * c.z; z.w = a.w * c.w;
            }
            *(float4*)(myStage + r * 128 + lane * 4) = z;
        }
        __syncwarp();

        u64 acc[8][2];

        // ---- GEMV 1 ----
#pragma unroll
        for (int r = 0; r < 8; r++) { acc[r][0] = 0ull; acc[r][1] = 0ull; }
#pragma unroll 1
        for (int k = 0; k < 128; k += 4) {
            float4 zq[8];
#pragma unroll
            for (int r = 0; r < 8; r++)
                zq[r] = *(const float4*)(myStage + r * 128 + k);
#pragma unroll
            for (int kk = 0; kk < 4; kk++) {
                ulonglong2 w = *(const ulonglong2*)(smW1 + (k + kk) * 128 + lane * 4);
#pragma unroll
                for (int r = 0; r < 8; r++) {
                    float zs = (kk == 0) ? zq[r].x : (kk == 1) ? zq[r].y
                             : (kk == 2) ? zq[r].z : zq[r].w;
                    u64 zz = pack_dup(zs);
                    ffma2(acc[r][0], zz, w.x);
                    ffma2(acc[r][1], zz, w.y);
                }
            }
        }
        __syncwarp();

        // ---- t1 = relu(acc + b1) -> restage (warp-local) ----
#pragma unroll
        for (int r = 0; r < 8; r++) {
            float lo0, hi0, lo1, hi1;
            unpack2(lo0, hi0, acc[r][0]);
            unpack2(lo1, hi1, acc[r][1]);
            float4 tq;
            tq.x = fmaxf(lo0 + b1v.x, 0.f);
            tq.y = fmaxf(hi0 + b1v.y, 0.f);
            tq.z = fmaxf(lo1 + b1v.z, 0.f);
            tq.w = fmaxf(hi1 + b1v.w, 0.f);
            *(float4*)(myStage + r * 128 + lane * 4) = tq;
        }
        __syncwarp();

        // ---- GEMV 2 ----
#pragma unroll
        for (int r = 0; r < 8; r++) { acc[r][0] = 0ull; acc[r][1] = 0ull; }
#pragma unroll 1
        for (int k = 0; k < 128; k += 4) {
            float4 zq[8];
#pragma unroll
            for (int r = 0; r < 8; r++)
                zq[r] = *(const float4*)(myStage + r * 128 + k);
#pragma unroll
            for (int kk = 0; kk < 4; kk++) {
                ulonglong2 w = *(const ulonglong2*)(smW2 + (k + kk) * 128 + lane * 4);
#pragma unroll
                for (int r = 0; r < 8; r++) {
                    float zs = (kk == 0) ? zq[r].x : (kk == 1) ? zq[r].y
                             : (kk == 2) ? zq[r].z : zq[r].w;
                    u64 zz = pack_dup(zs);
                    ffma2(acc[r][0], zz, w.x);
                    ffma2(acc[r][1], zz, w.y);
                }
            }
        }

        // ---- out = relu(acc + b2) . Wd3 + bd3 ----
#pragma unroll
        for (int r = 0; r < 8; r++) {
            float t0, t1, t2, t3;
            unpack2(t0, t1, acc[r][0]);
            unpack2(t2, t3, acc[r][1]);
            t0 = fmaxf(t0 + b2v.x, 0.f);
            t1 = fmaxf(t1 + b2v.y, 0.f);
            t2 = fmaxf(t2 + b2v.z, 0.f);
            t3 = fmaxf(t3 + b2v.w, 0.f);
            float partial = t0 * w3v.x + t1 * w3v.y + t2 * w3v.z + t3 * w3v.w;
#pragma unroll
            for (int off = 16; off > 0; off >>= 1)
                partial += __shfl_xor_sync(0xffffffffu, partial, off);
            int p = base + r;
            if (lane == 0 && p < bend) out[p] = partial + b3;
        }
        __syncwarp();
    }
}

// ============================================================================
// launch
// ============================================================================
extern "C" void kernel_launch(void* const* d_in, const int* in_sizes, int n_in,
                              void* d_out, int out_size)
{
    const float* x    = (const float*)d_in[0];
    const int*   esrc = (const int*)  d_in[1];
    const int*   edst = (const int*)  d_in[2];
    const int*   ps   = (const int*)  d_in[3];
    const int*   pd   = (const int*)  d_in[4];
    const int*   ns   = (const int*)  d_in[5];
    const int*   nd   = (const int*)  d_in[6];
    const float* Ws1  = (const float*)d_in[7];
    const float* Wn1  = (const float*)d_in[8];
    const float* b1   = (const float*)d_in[9];
    const float* Ws2  = (const float*)d_in[10];
    const float* Wn2  = (const float*)d_in[11];
    const float* b2   = (const float*)d_in[12];
    const float* Wd1  = (const float*)d_in[13];
    const float* bd1  = (const float*)d_in[14];
    const float* Wd2  = (const float*)d_in[15];
    const float* bd2  = (const float*)d_in[16];
    const float* Wd3  = (const float*)d_in[17];
    const float* bd3  = (const float*)d_in[18];
    float* out = (float*)d_out;

    void *cntPtr, *curPtr, *h1Ptr, *h2Ptr;
    cudaGetSymbolAddress(&cntPtr, g_cnt);
    cudaGetSymbolAddress(&curPtr, g_cur);
    cudaGetSymbolAddress(&h1Ptr,  g_h1);
    cudaGetSymbolAddress(&h2Ptr,  g_h2);

    int nsm = 148;
    cudaDeviceGetAttribute(&nsm, cudaDevAttrMultiProcessorCount, 0);

    int rpb_sage = (((NN + nsm - 1) / nsm) + 7) & ~7;
    int rpb_dec  = (((2 * PP + nsm - 1) / nsm) + 7) & ~7;

    const int SAGE_SMEM = 256 * 128 * 4 + 16 * 8 * 128 * 4;       // 196608 B
    const int DEC_SMEM  = 2 * 128 * 128 * 4 + 16 * 8 * 128 * 4;   // 196608 B
    cudaFuncSetAttribute(sage_linear_kernel<true>,
                         cudaFuncAttributeMaxDynamicSharedMemorySize, SAGE_SMEM);
    cudaFuncSetAttribute(sage_linear_kernel<false>,
                         cudaFuncAttributeMaxDynamicSharedMemorySize, SAGE_SMEM);
    cudaFuncSetAttribute(decoder_kernel,
                         cudaFuncAttributeMaxDynamicSharedMemorySize, DEC_SMEM);

    // ---- CSR build ----
    cudaMemsetAsync(cntPtr, 0, sizeof(int) * NN, 0);
    cudaMemsetAsync(curPtr, 0, sizeof(int) * NN, 0);
    count_kernel<<<(EE + 255) / 256, 256>>>(edst);
    scan_kernel<<<1, 1024>>>();
    fill_kernel<<<(EE + 255) / 256, 256>>>(esrc, edst);

    // ---- layer 1 (fused aggregate) ----
    sage_linear_kernel<true><<<nsm, 512, SAGE_SMEM>>>(x, Ws1, Wn1, b1,
                                                      (float*)h1Ptr, rpb_sage);
    // ---- layer 2 (fused aggregate) ----
    sage_linear_kernel<false><<<nsm, 512, SAGE_SMEM>>>((const float*)h1Ptr,
                                                       Ws2, Wn2, b2,
                                                       (float*)h2Ptr, rpb_sage);
    // ---- decoder ----
    decoder_kernel<<<nsm, 512, DEC_SMEM>>>((const float*)h2Ptr,
                                           ps, pd, ns, nd,
                                           Wd1, bd1, Wd2, bd2, Wd3, bd3, out,
                                           rpb_dec);
}

// round 10
// speedup vs baseline: 1.7430x; 1.7430x over previous
#include <cuda_runtime.h>
#include <cstdint>

#define NN 50000
#define EE 600000
#define PP 100000
#define FD 128

// ---- device scratch ----
__device__ float g_agg[NN * FD];     // MEAN aggregate
__device__ float g_h1[NN * FD];
__device__ float g_h2[NN * FD];
__device__ int   g_cnt[NN];          // restored to 0 by fill_kernel each run
__device__ int   g_rowstart[NN + 1];
__device__ int   g_csr[EE];

typedef unsigned long long u64;

__device__ __forceinline__ void ffma2(u64& d, u64 a, u64 b) {
    asm("fma.rn.f32x2 %0, %1, %2, %0;" : "+l"(d) : "l"(a), "l"(b));
}
__device__ __forceinline__ void unpack2(float& lo, float& hi, u64 v) {
    asm("mov.b64 {%0, %1}, %2;" : "=f"(lo), "=f"(hi) : "l"(v));
}
__device__ __forceinline__ u64 pack_dup(float a) {
    u64 r;
    asm("mov.b64 %0, {%1, %1};" : "=l"(r) : "f"(a));
    return r;
}

// ============================================================================
// CSR build: count -> scan -> fill (fill restores g_cnt to zero)
// ============================================================================
__global__ void count_kernel(const int* __restrict__ dst)
{
    int e = blockIdx.x * blockDim.x + threadIdx.x;
    if (e < EE) atomicAdd(&g_cnt[dst[e]], 1);
}

__global__ void __launch_bounds__(1024, 1) scan_kernel()
{
    __shared__ int wsum[32];
    __shared__ int carry;
    int tid = threadIdx.x, lane = tid & 31, w = tid >> 5;
    if (tid == 0) carry = 0;
    __syncthreads();
    for (int base = 0; base < NN; base += 1024) {
        int i = base + tid;
        int v = (i < NN) ? g_cnt[i] : 0;
        int s = v;
#pragma unroll
        for (int off = 1; off < 32; off <<= 1) {
            int t = __shfl_up_sync(0xffffffffu, s, off);
            if (lane >= off) s += t;
        }
        if (lane == 31) wsum[w] = s;
        __syncthreads();
        if (w == 0) {
            int ws = wsum[lane];
#pragma unroll
            for (int off = 1; off < 32; off <<= 1) {
                int t = __shfl_up_sync(0xffffffffu, ws, off);
                if (lane >= off) ws += t;
            }
            wsum[lane] = ws;
        }
        __syncthreads();
        int prev = (w > 0) ? wsum[w - 1] : 0;
        int incl = carry + prev + s;
        if (i < NN) g_rowstart[i + 1] = incl;
        int chunk_total = wsum[31];
        __syncthreads();
        if (tid == 0) carry += chunk_total;
        __syncthreads();
    }
    if (threadIdx.x == 0) g_rowstart[0] = 0;
}

__global__ void fill_kernel(const int* __restrict__ src,
                            const int* __restrict__ dst)
{
    int e = blockIdx.x * blockDim.x + threadIdx.x;
    if (e >= EE) return;
    int d = dst[e];
    int p = atomicAdd(&g_cnt[d], -1) - 1;     // leaves g_cnt[d] at 0 when done
    g_csr[g_rowstart[d] + p] = src[e];
}

// ============================================================================
// Aggregate (R8 exact): one warp per node, gather + accumulate, write MEAN.
// ============================================================================
__global__ void aggregate_kernel(const float* __restrict__ h)
{
    int gw   = (blockIdx.x * blockDim.x + threadIdx.x) >> 5;
    int lane = threadIdx.x & 31;
    if (gw >= NN) return;
    int beg = g_rowstart[gw], end = g_rowstart[gw + 1];
    const float* hp = h + lane * 4;
    float4 acc = make_float4(0.f, 0.f, 0.f, 0.f);
    int e = beg;
    for (; e + 1 < end; e += 2) {
        int s0 = g_csr[e], s1 = g_csr[e + 1];
        float4 v0 = *(const float4*)(hp + s0 * FD);
        float4 v1 = *(const float4*)(hp + s1 * FD);
        acc.x += v0.x + v1.x; acc.y += v0.y + v1.y;
        acc.z += v0.z + v1.z; acc.w += v0.w + v1.w;
    }
    if (e < end) {
        int s0 = g_csr[e];
        float4 v0 = *(const float4*)(hp + s0 * FD);
        acc.x += v0.x; acc.y += v0.y; acc.z += v0.z; acc.w += v0.w;
    }
    float rd = 1.0f / fmaxf((float)(end - beg), 1.0f);
    acc.x *= rd; acc.y *= rd; acc.z *= rd; acc.w *= rd;
    *(float4*)(g_agg + gw * FD + lane * 4) = acc;
}

// ============================================================================
// Half-K SAGE linear (frozen R8 micro-kernel, single K=128 pass).
// ADD=false: out = src @ W + b         (self half)
// ADD=true : out = out + src @ W, then optional RELU   (neigh half)
// ============================================================================
template <bool ADD, bool RELU>
__global__ void __launch_bounds__(512, 1)
sage_half_kernel(const float* __restrict__ src,
                 const float* __restrict__ W,
                 const float* __restrict__ b,
                 float* __restrict__ out,
                 int rpb)
{
    extern __shared__ float sm[];
    float* smW   = sm;                 // [128][128]
    float* stage = sm + 128 * 128;     // [16][8][128]

    int tid  = threadIdx.x;
    int lane = tid & 31;
    int warp = tid >> 5;

    for (int i = tid; i < (128 * 128) / 4; i += blockDim.x)
        ((float4*)smW)[i] = ((const float4*)W)[i];
    __syncthreads();

    int bstart = blockIdx.x * rpb;
    int bend   = min(bstart + rpb, NN);

    float4 bias = make_float4(0.f, 0.f, 0.f, 0.f);
    if (!ADD) bias = *(const float4*)(b + lane * 4);
    float* myStage = stage + warp * (8 * 128);

    for (int base = bstart + warp * 8; base < bend; base += 128) {

        // ---- stage 8 rows (warp-local) ----
#pragma unroll
        for (int r = 0; r < 8; r++) {
            int row = base + r;
            float4 v = make_float4(0.f, 0.f, 0.f, 0.f);
            if (row < bend)
                v = *(const float4*)(src + row * FD + lane * 4);
            *(float4*)(myStage + r * 128 + lane * 4) = v;
        }
        __syncwarp();

        u64 acc[8][2];
#pragma unroll
        for (int r = 0; r < 8; r++) { acc[r][0] = 0ull; acc[r][1] = 0ull; }

#pragma unroll 1
        for (int k = 0; k < 128; k += 4) {
            float4 xq[8];
#pragma unroll
            for (int r = 0; r < 8; r++)
                xq[r] = *(const float4*)(myStage + r * 128 + k);
#pragma unroll
            for (int kk = 0; kk < 4; kk++) {
                ulonglong2 w = *(const ulonglong2*)(smW + (k + kk) * 128 + lane * 4);
#pragma unroll
                for (int r = 0; r < 8; r++) {
                    float xs = (kk == 0) ? xq[r].x : (kk == 1) ? xq[r].y
                             : (kk == 2) ? xq[r].z : xq[r].w;
                    u64 xx = pack_dup(xs);
                    ffma2(acc[r][0], xx, w.x);
                    ffma2(acc[r][1], xx, w.y);
                }
            }
        }
        __syncwarp();

#pragma unroll
        for (int r = 0; r < 8; r++) {
            int row = base + r;
            if (row < bend) {
                float4 o;
                unpack2(o.x, o.y, acc[r][0]);
                unpack2(o.z, o.w, acc[r][1]);
                float4* op = (float4*)(out + row * FD + lane * 4);
                if (ADD) {
                    float4 prev = *op;
                    o.x += prev.x; o.y += prev.y; o.z += prev.z; o.w += prev.w;
                } else {
                    o.x += bias.x; o.y += bias.y; o.z += bias.z; o.w += bias.w;
                }
                if (RELU) {
                    o.x = fmaxf(o.x, 0.f); o.y = fmaxf(o.y, 0.f);
                    o.z = fmaxf(o.z, 0.f); o.w = fmaxf(o.w, 0.f);
                }
                *op = o;
            }
        }
    }
}

// ============================================================================
// Fused decoder (R8 form, proven)
// ============================================================================
__global__ void __launch_bounds__(512, 1)
decoder_kernel(const float* __restrict__ h,
               const int* __restrict__ ps, const int* __restrict__ pd,
               const int* __restrict__ ns, const int* __restrict__ nd,
               const float* __restrict__ Wd1, const float* __restrict__ bd1,
               const float* __restrict__ Wd2, const float* __restrict__ bd2,
               const float* __restrict__ Wd3, const float* __restrict__ bd3,
               float* __restrict__ out,
               int rpb)
{
    extern __shared__ float sm[];
    float* smW1  = sm;                 // [128][128]
    float* smW2  = sm + 128 * 128;     // [128][128]
    float* stage = sm + 2 * 128 * 128; // [16][8][128]

    int tid  = threadIdx.x;
    int lane = tid & 31;
    int warp = tid >> 5;

    for (int i = tid; i < (128 * 128) / 4; i += blockDim.x) {
        ((float4*)smW1)[i] = ((const float4*)Wd1)[i];
        ((float4*)smW2)[i] = ((const float4*)Wd2)[i];
    }
    __syncthreads();

    float4 b1v = *(const float4*)(bd1 + lane * 4);
    float4 b2v = *(const float4*)(bd2 + lane * 4);
    float4 w3v = *(const float4*)(Wd3 + lane * 4);
    float  b3  = bd3[0];

    float* myStage = stage + warp * (8 * 128);
    const int total = 2 * PP;

    int bstart = blockIdx.x * rpb;
    int bend   = min(bstart + rpb, total);

    for (int base = bstart + warp * 8; base < bend; base += 128) {
#pragma unroll
        for (int r = 0; r < 8; r++) {
            int p = base + r;
            float4 z = make_float4(0.f, 0.f, 0.f, 0.f);
            if (p < bend) {
                int s, d;
                if (p < PP) { s = ps[p]; d = pd[p]; }
                else        { s = ns[p - PP]; d = nd[p - PP]; }
                float4 a = *(const float4*)(h + s * FD + lane * 4);
                float4 c = *(const float4*)(h + d * FD + lane * 4);
                z.x = a.x * c.x; z.y = a.y * c.y;
                z.z = a.z * c.z; z.w = a.w * c.w;
            }
            *(float4*)(myStage + r * 128 + lane * 4) = z;
        }
        __syncwarp();

        u64 acc[8][2];

        // ---- GEMV 1 ----
#pragma unroll
        for (int r = 0; r < 8; r++) { acc[r][0] = 0ull; acc[r][1] = 0ull; }
#pragma unroll 1
        for (int k = 0; k < 128; k += 4) {
            float4 zq[8];
#pragma unroll
            for (int r = 0; r < 8; r++)
                zq[r] = *(const float4*)(myStage + r * 128 + k);
#pragma unroll
            for (int kk = 0; kk < 4; kk++) {
                ulonglong2 w = *(const ulonglong2*)(smW1 + (k + kk) * 128 + lane * 4);
#pragma unroll
                for (int r = 0; r < 8; r++) {
                    float zs = (kk == 0) ? zq[r].x : (kk == 1) ? zq[r].y
                             : (kk == 2) ? zq[r].z : zq[r].w;
                    u64 zz = pack_dup(zs);
                    ffma2(acc[r][0], zz, w.x);
                    ffma2(acc[r][1], zz, w.y);
                }
            }
        }
        __syncwarp();

        // ---- t1 = relu(acc + b1) -> restage ----
#pragma unroll
        for (int r = 0; r < 8; r++) {
            float lo0, hi0, lo1, hi1;
            unpack2(lo0, hi0, acc[r][0]);
            unpack2(lo1, hi1, acc[r][1]);
            float4 tq;
            tq.x = fmaxf(lo0 + b1v.x, 0.f);
            tq.y = fmaxf(hi0 + b1v.y, 0.f);
            tq.z = fmaxf(lo1 + b1v.z, 0.f);
            tq.w = fmaxf(hi1 + b1v.w, 0.f);
            *(float4*)(myStage + r * 128 + lane * 4) = tq;
        }
        __syncwarp();

        // ---- GEMV 2 ----
#pragma unroll
        for (int r = 0; r < 8; r++) { acc[r][0] = 0ull; acc[r][1] = 0ull; }
#pragma unroll 1
        for (int k = 0; k < 128; k += 4) {
            float4 zq[8];
#pragma unroll
            for (int r = 0; r < 8; r++)
                zq[r] = *(const float4*)(myStage + r * 128 + k);
#pragma unroll
            for (int kk = 0; kk < 4; kk++) {
                ulonglong2 w = *(const ulonglong2*)(smW2 + (k + kk) * 128 + lane * 4);
#pragma unroll
                for (int r = 0; r < 8; r++) {
                    float zs = (kk == 0) ? zq[r].x : (kk == 1) ? zq[r].y
                             : (kk == 2) ? zq[r].z : zq[r].w;
                    u64 zz = pack_dup(zs);
                    ffma2(acc[r][0], zz, w.x);
                    ffma2(acc[r][1], zz, w.y);
                }
            }
        }

        // ---- out = relu(acc + b2) . Wd3 + bd3 ----
#pragma unroll
        for (int r = 0; r < 8; r++) {
            float t0, t1, t2, t3;
            unpack2(t0, t1, acc[r][0]);
            unpack2(t2, t3, acc[r][1]);
            t0 = fmaxf(t0 + b2v.x, 0.f);
            t1 = fmaxf(t1 + b2v.y, 0.f);
            t2 = fmaxf(t2 + b2v.z, 0.f);
            t3 = fmaxf(t3 + b2v.w, 0.f);
            float partial = t0 * w3v.x + t1 * w3v.y + t2 * w3v.z + t3 * w3v.w;
#pragma unroll
            for (int off = 16; off > 0; off >>= 1)
                partial += __shfl_xor_sync(0xffffffffu, partial, off);
            int p = base + r;
            if (lane == 0 && p < bend) out[p] = partial + b3;
        }
        __syncwarp();
    }
}

// ============================================================================
// launch — two-stream fork/join: aggregates hidden under self-GEMMs
// ============================================================================
extern "C" void kernel_launch(void* const* d_in, const int* in_sizes, int n_in,
                              void* d_out, int out_size)
{
    const float* x    = (const float*)d_in[0];
    const int*   esrc = (const int*)  d_in[1];
    const int*   edst = (const int*)  d_in[2];
    const int*   ps   = (const int*)  d_in[3];
    const int*   pd   = (const int*)  d_in[4];
    const int*   ns   = (const int*)  d_in[5];
    const int*   nd   = (const int*)  d_in[6];
    const float* Ws1  = (const float*)d_in[7];
    const float* Wn1  = (const float*)d_in[8];
    const float* b1   = (const float*)d_in[9];
    const float* Ws2  = (const float*)d_in[10];
    const float* Wn2  = (const float*)d_in[11];
    const float* b2   = (const float*)d_in[12];
    const float* Wd1  = (const float*)d_in[13];
    const float* bd1  = (const float*)d_in[14];
    const float* Wd2  = (const float*)d_in[15];
    const float* bd2  = (const float*)d_in[16];
    const float* Wd3  = (const float*)d_in[17];
    const float* bd3  = (const float*)d_in[18];
    float* out = (float*)d_out;

    void *aggPtr, *h1Ptr, *h2Ptr;
    cudaGetSymbolAddress(&aggPtr, g_agg);
    cudaGetSymbolAddress(&h1Ptr,  g_h1);
    cudaGetSymbolAddress(&h2Ptr,  g_h2);
    float* h1 = (float*)h1Ptr;
    float* h2 = (float*)h2Ptr;
    float* agg = (float*)aggPtr;

    int nsm = 148;
    cudaDeviceGetAttribute(&nsm, cudaDevAttrMultiProcessorCount, 0);

    int rpb_sage = (((NN + nsm - 1) / nsm) + 7) & ~7;
    int rpb_dec  = (((2 * PP + nsm - 1) / nsm) + 7) & ~7;

    const int HALF_SMEM = 128 * 128 * 4 + 16 * 8 * 128 * 4;       // 131072 B
    const int DEC_SMEM  = 2 * 128 * 128 * 4 + 16 * 8 * 128 * 4;   // 196608 B
    cudaFuncSetAttribute(sage_half_kernel<false, false>,
                         cudaFuncAttributeMaxDynamicSharedMemorySize, HALF_SMEM);
    cudaFuncSetAttribute(sage_half_kernel<true, true>,
                         cudaFuncAttributeMaxDynamicSharedMemorySize, HALF_SMEM);
    cudaFuncSetAttribute(sage_half_kernel<true, false>,
                         cudaFuncAttributeMaxDynamicSharedMemorySize, HALF_SMEM);
    cudaFuncSetAttribute(decoder_kernel,
                         cudaFuncAttributeMaxDynamicSharedMemorySize, DEC_SMEM);

    // lazy host-object init (streams/events allocate no tracked device memory)
    static cudaStream_t sB = nullptr;
    static cudaEvent_t evFork = nullptr, evAgg1 = nullptr,
                       evH1 = nullptr, evAgg2 = nullptr;
    if (sB == nullptr) {
        cudaStreamCreateWithFlags(&sB, cudaStreamNonBlocking);
        cudaEventCreateWithFlags(&evFork, cudaEventDisableTiming);
        cudaEventCreateWithFlags(&evAgg1, cudaEventDisableTiming);
        cudaEventCreateWithFlags(&evH1,   cudaEventDisableTiming);
        cudaEventCreateWithFlags(&evAgg2, cudaEventDisableTiming);
    }

    int ablocks = (NN * 32 + 255) / 256;

    // ---- fork ----
    cudaEventRecord(evFork, 0);
    cudaStreamWaitEvent(sB, evFork, 0);

    // streamB: CSR build + aggregate layer 1 (g_cnt self-restores to 0)
    count_kernel<<<(EE + 255) / 256, 256, 0, sB>>>(edst);
    scan_kernel<<<1, 1024, 0, sB>>>();
    fill_kernel<<<(EE + 255) / 256, 256, 0, sB>>>(esrc, edst);
    aggregate_kernel<<<ablocks, 256, 0, sB>>>(x);
    cudaEventRecord(evAgg1, sB);

    // streamA (main): self half of layer 1, concurrent with CSR+agg1
    sage_half_kernel<false, false><<<nsm, 512, HALF_SMEM>>>(x, Ws1, b1, h1,
                                                            rpb_sage);
    cudaStreamWaitEvent(0, evAgg1, 0);
    sage_half_kernel<true, true><<<nsm, 512, HALF_SMEM>>>(agg, Wn1, b1, h1,
                                                          rpb_sage);
    cudaEventRecord(evH1, 0);

    // streamB: aggregate layer 2 (needs h1), concurrent with sage2_self
    cudaStreamWaitEvent(sB, evH1, 0);
    aggregate_kernel<<<ablocks, 256, 0, sB>>>(h1);
    cudaEventRecord(evAgg2, sB);

    // streamA: self half of layer 2
    sage_half_kernel<false, false><<<nsm, 512, HALF_SMEM>>>(h1, Ws2, b2, h2,
                                                            rpb_sage);
    cudaStreamWaitEvent(0, evAgg2, 0);
    sage_half_kernel<true, false><<<nsm, 512, HALF_SMEM>>>(agg, Wn2, b2, h2,
                                                           rpb_sage);

    // decoder
    decoder_kernel<<<nsm, 512, DEC_SMEM>>>(h2, ps, pd, ns, nd,
                                           Wd1, bd1, Wd2, bd2, Wd3, bd3, out,
                                           rpb_dec);
}